// round 13
// baseline (speedup 1.0000x reference)
#include <cuda_runtime.h>
#include <cuda_bf16.h>
#include <cstdint>

// Fused autoencoder fwd+Jacobians: warp mma.sync bf16-split, 3-GEMM chain.
// GEMM1: Z = H*W2^T (N=16). GEMM2: AB = S*[P0|P1] (N=32, premultiplied).
// GEMM3: [y0 y1 J00 J01 J10 J11] = [h2|sa|sb] * W3-block (K=48, N=8),
//        A built in-register from GEMM1/2 C-frags (C-frag == A-frag layout).
// Outputs: theta[N,2] | J_h[N,2,2] | q_hat[N,2] | J_h_dec[N,2,2] | J_h_ana[N,2,2]

#define STG_STRIDE 144
#define SM_STG  0                       // 4 warps * 32 rows * 144 = 18432
#define SM_ZB   18432                   // 2E * (hi768+lo768) = 3072
#define SM_ABB  (18432 + 3072)          // 2E * (hi1280+lo1280) = 5120
#define SM_B3   (SM_ABB + 5120)         // 2E * (hi768+lo768) = 3072
#define SM_EWF  (SM_B3 + 3072)          // 2E * 18 floats
#define SM_TOT  (SM_EWF + 160)

__constant__ float CWf[96];             // [E*48]: w1 interleaved(32), b1(16)
__device__   float g_scr[96];

__device__ __forceinline__ uint32_t s2u(const void* p) {
    uint32_t a;
    asm("{.reg .u64 t; cvta.to.shared.u64 t,%1; cvt.u32.u64 %0,t;}" : "=r"(a) : "l"(p));
    return a;
}
__device__ __forceinline__ void ldsm4(uint32_t& r0, uint32_t& r1, uint32_t& r2, uint32_t& r3, uint32_t a) {
    asm volatile("ldmatrix.sync.aligned.m8n8.x4.shared.b16 {%0,%1,%2,%3},[%4];"
                 : "=r"(r0), "=r"(r1), "=r"(r2), "=r"(r3) : "r"(a));
}
__device__ __forceinline__ void ldsm4t(uint32_t& r0, uint32_t& r1, uint32_t& r2, uint32_t& r3, uint32_t a) {
    asm volatile("ldmatrix.sync.aligned.m8n8.x4.trans.shared.b16 {%0,%1,%2,%3},[%4];"
                 : "=r"(r0), "=r"(r1), "=r"(r2), "=r"(r3) : "r"(a));
}
__device__ __forceinline__ void ldsm2t(uint32_t& r0, uint32_t& r1, uint32_t a) {
    asm volatile("ldmatrix.sync.aligned.m8n8.x2.trans.shared.b16 {%0,%1},[%2];"
                 : "=r"(r0), "=r"(r1) : "r"(a));
}
__device__ __forceinline__ void mma16816(float* d, const uint32_t* a, uint32_t b0, uint32_t b1) {
    asm volatile("mma.sync.aligned.m16n8k16.row.col.f32.bf16.bf16.f32 "
                 "{%0,%1,%2,%3},{%4,%5,%6,%7},{%8,%9},{%0,%1,%2,%3};"
                 : "+f"(d[0]), "+f"(d[1]), "+f"(d[2]), "+f"(d[3])
                 : "r"(a[0]), "r"(a[1]), "r"(a[2]), "r"(a[3]), "r"(b0), "r"(b1));
}
__device__ __forceinline__ void act(float z, float& h, float& s) {
    const float L2E = 1.442695041f, LN2 = 0.6931471806f;
    float t, g;
    asm("ex2.approx.ftz.f32 %0,%1;" : "=f"(t) : "f"(fabsf(z) * -L2E));
    asm("lg2.approx.ftz.f32 %0,%1;" : "=f"(g) : "f"(1.0f + t));
    h = fmaf(g, LN2, fmaxf(z, 0.0f));
    asm("ex2.approx.ftz.f32 %0,%1;" : "=f"(s) : "f"(fmaf(fminf(z, 0.0f), L2E, -g)));
}
__device__ __forceinline__ float trhi(float v) { return __uint_as_float(__float_as_uint(v) & 0xffff0000u); }
__device__ __forceinline__ uint32_t bfp(float a, float b) {  // a -> low half
    uint32_t r;
    asm("cvt.rn.bf16x2.f32 %0,%1,%2;" : "=r"(r) : "f"(b), "f"(a));
    return r;
}
__device__ __forceinline__ void packsplit(float a, float b, uint32_t& hi, uint32_t& lo) {
    float ah = trhi(a), bh = trhi(b);
    hi = bfp(ah, bh);
    lo = bfp(a - ah, b - bh);
}

struct PC {
    char*    rowPtr;
    uint32_t aBase, zBase, abBase, b3Base, b3Base2;
    char*    smp;
    int l, m, g, own;
};

// One MLP phase for a 32-sample warp tile.
__device__ void phase(const PC& c, int E, bool isEnc, float x0, float x1,
                      int tb, int N, float* out, float& th0, float& th1)
{
    const float* o = CWf + E * 48;
    const float* ew = (const float*)(c.smp + SM_EWF) + E * 18;
    float b2a = ew[2 * c.m], b2b = ew[2 * c.m + 1];
    float b2c = ew[2 * c.m + 8], b2d = ew[2 * c.m + 9];
    float b30 = ew[16], b31 = ew[17];

    // ---- layer 1 (own row) ----
    float hv[16], sv[16];
#pragma unroll
    for (int i = 0; i < 16; ++i) {
        float z = fmaf(o[2 * i], x0, fmaf(o[2 * i + 1], x1, o[32 + i]));
        act(z, hv[i], sv[i]);
    }
    uint32_t ph[8], pl[8], qh[8], ql[8];
#pragma unroll
    for (int k = 0; k < 8; ++k) {
        packsplit(hv[2 * k], hv[2 * k + 1], ph[k], pl[k]);
        packsplit(sv[2 * k], sv[2 * k + 1], qh[k], ql[k]);
    }
    __syncwarp();
    uint4* rw = (uint4*)c.rowPtr;
    rw[0] = make_uint4(ph[0], ph[1], ph[2], ph[3]);
    rw[1] = make_uint4(ph[4], ph[5], ph[6], ph[7]);
    rw[2] = make_uint4(pl[0], pl[1], pl[2], pl[3]);
    rw[3] = make_uint4(pl[4], pl[5], pl[6], pl[7]);
    rw[4] = make_uint4(qh[0], qh[1], qh[2], qh[3]);
    rw[5] = make_uint4(qh[4], qh[5], qh[6], qh[7]);
    rw[6] = make_uint4(ql[0], ql[1], ql[2], ql[3]);
    rw[7] = make_uint4(ql[4], ql[5], ql[6], ql[7]);
    __syncwarp();

    // ---- B fragments ----
    uint32_t zh[4], zl[4], abh[8], abl[8], b3h[6], b3l[6];
    uint32_t za = c.zBase + E * 1536;
    ldsm4t(zh[0], zh[1], zh[2], zh[3], za);
    ldsm4t(zl[0], zl[1], zl[2], zl[3], za + 768);
    uint32_t aa = c.abBase + E * 2560;
    ldsm4t(abh[0], abh[1], abh[2], abh[3], aa);
    ldsm4t(abh[4], abh[5], abh[6], abh[7], aa + 32);
    ldsm4t(abl[0], abl[1], abl[2], abl[3], aa + 1280);
    ldsm4t(abl[4], abl[5], abl[6], abl[7], aa + 1280 + 32);
    uint32_t ba  = c.b3Base  + E * 1536;   // rows 0-31 (lane-dependent, x4)
    uint32_t ba2 = c.b3Base2 + E * 1536;   // rows 32-47 (lanes 0-15, x2)
    ldsm4t(b3h[0], b3h[1], b3h[2], b3h[3], ba);
    ldsm2t(b3h[4], b3h[5], ba2);
    ldsm4t(b3l[0], b3l[1], b3l[2], b3l[3], ba + 768);
    ldsm2t(b3l[4], b3l[5], ba2 + 768);

    const size_t Ns = (size_t)N;
    float2* oY = (float2*)(isEnc ? out : out + 6 * Ns);          // theta / qhat
    float2* oJ = (float2*)(isEnc ? out + 2 * Ns : out + 8 * Ns); // Jh / Jd

#pragma unroll
    for (int rb = 0; rb < 2; ++rb) {
        uint32_t Hh[4], Hl[4], Sh[4], Sl[4];
        uint32_t baA = c.aBase + rb * (16 * STG_STRIDE);
        ldsm4(Hh[0], Hh[1], Hh[2], Hh[3], baA + 0);
        ldsm4(Hl[0], Hl[1], Hl[2], Hl[3], baA + 32);
        ldsm4(Sh[0], Sh[1], Sh[2], Sh[3], baA + 64);
        ldsm4(Sl[0], Sl[1], Sl[2], Sl[3], baA + 96);

        float Zc[2][4] = {};
        float Ac[4][4] = {};
        mma16816(Zc[0], Hh, zh[0], zh[1]);
        mma16816(Zc[1], Hh, zh[2], zh[3]);
        mma16816(Zc[0], Hh, zl[0], zl[1]);
        mma16816(Zc[1], Hh, zl[2], zl[3]);
        mma16816(Zc[0], Hl, zh[0], zh[1]);
        mma16816(Zc[1], Hl, zh[2], zh[3]);
#pragma unroll
        for (int cb = 0; cb < 4; ++cb) {
            mma16816(Ac[cb], Sh, abh[2 * cb], abh[2 * cb + 1]);
            mma16816(Ac[cb], Sh, abl[2 * cb], abl[2 * cb + 1]);
            mma16816(Ac[cb], Sl, abh[2 * cb], abh[2 * cb + 1]);
        }

        // ---- in-register epilogue -> GEMM3 A fragments ----
        float h2[8], s2[8];
        {
            float zz[8] = { Zc[0][0] + b2a, Zc[0][1] + b2b, Zc[0][2] + b2a, Zc[0][3] + b2b,
                            Zc[1][0] + b2c, Zc[1][1] + b2d, Zc[1][2] + b2c, Zc[1][3] + b2d };
#pragma unroll
            for (int i = 0; i < 8; ++i) act(zz[i], h2[i], s2[i]);
        }
        float C3[4] = {};
        uint32_t Ah[4], Al[4];
        // chunk0: h2
        packsplit(h2[0], h2[1], Ah[0], Al[0]);
        packsplit(h2[2], h2[3], Ah[1], Al[1]);
        packsplit(h2[4], h2[5], Ah[2], Al[2]);
        packsplit(h2[6], h2[7], Ah[3], Al[3]);
        mma16816(C3, Ah, b3h[0], b3h[1]);
        mma16816(C3, Al, b3h[0], b3h[1]);
        mma16816(C3, Ah, b3l[0], b3l[1]);
        // chunk1: sa = s2 * a  (a at Ac[0] j<8, Ac[2] j>=8)
        packsplit(s2[0] * Ac[0][0], s2[1] * Ac[0][1], Ah[0], Al[0]);
        packsplit(s2[2] * Ac[0][2], s2[3] * Ac[0][3], Ah[1], Al[1]);
        packsplit(s2[4] * Ac[2][0], s2[5] * Ac[2][1], Ah[2], Al[2]);
        packsplit(s2[6] * Ac[2][2], s2[7] * Ac[2][3], Ah[3], Al[3]);
        mma16816(C3, Ah, b3h[2], b3h[3]);
        mma16816(C3, Al, b3h[2], b3h[3]);
        mma16816(C3, Ah, b3l[2], b3l[3]);
        // chunk2: sb  (b at Ac[1], Ac[3])
        packsplit(s2[0] * Ac[1][0], s2[1] * Ac[1][1], Ah[0], Al[0]);
        packsplit(s2[2] * Ac[1][2], s2[3] * Ac[1][3], Ah[1], Al[1]);
        packsplit(s2[4] * Ac[3][0], s2[5] * Ac[3][1], Ah[2], Al[2]);
        packsplit(s2[6] * Ac[3][2], s2[7] * Ac[3][3], Ah[3], Al[3]);
        mma16816(C3, Ah, b3h[4], b3h[5]);
        mma16816(C3, Al, b3h[4], b3h[5]);
        mma16816(C3, Ah, b3l[4], b3l[5]);

        if (c.m == 0) { C3[0] += b30; C3[1] += b31; C3[2] += b30; C3[3] += b31; }

        const int r1 = tb + rb * 16 + c.g;
        const int r2 = r1 + 8;
        if (c.m == 0) {
            if (r1 < N) oY[r1] = make_float2(C3[0], C3[1]);
            if (r2 < N) oY[r2] = make_float2(C3[2], C3[3]);
        } else if (c.m == 1) {          // (J00,J01)
            if (r1 < N) oJ[2 * r1] = make_float2(C3[0], C3[1]);
            if (r2 < N) oJ[2 * r2] = make_float2(C3[2], C3[3]);
        } else if (c.m == 2) {          // (J10,J11)
            if (r1 < N) oJ[2 * r1 + 1] = make_float2(C3[0], C3[1]);
            if (r2 < N) oJ[2 * r2 + 1] = make_float2(C3[2], C3[3]);
        }

        if (isEnc) {  // broadcast theta to owner lanes
            int src = 4 * (c.own & 7);
            float s0 = __shfl_sync(~0u, C3[0], src);
            float s1 = __shfl_sync(~0u, C3[1], src);
            float s2v = __shfl_sync(~0u, C3[2], src);
            float s3 = __shfl_sync(~0u, C3[3], src);
            if ((c.own >> 4) == rb) {
                bool lo8 = (c.own & 15) < 8;
                th0 = lo8 ? s0 : s2v;
                th1 = lo8 ? s1 : s3;
            }
        }
    }
}

__global__ void __launch_bounds__(128, 4) ae_mma_kernel(
    const float* __restrict__ q,
    const float* __restrict__ ew1, const float* __restrict__ eb1,
    const float* __restrict__ ew2, const float* __restrict__ eb2,
    const float* __restrict__ ew3, const float* __restrict__ eb3,
    const float* __restrict__ dw1, const float* __restrict__ db1,
    const float* __restrict__ dw2, const float* __restrict__ db2,
    const float* __restrict__ dw3, const float* __restrict__ db3,
    float* __restrict__ out, int N)
{
    __shared__ __align__(16) char sm[SM_TOT];
    const int t = threadIdx.x;
    const float* W1g[2] = {ew1, dw1};
    const float* W2g[2] = {ew2, dw2};
    const float* W3g[2] = {ew3, dw3};

    // Bz: identity columns, K-major 16x16, stride 48
    for (int idx = t; idx < 512; idx += 128) {
        int E = idx >> 8, r = idx & 255, k = r >> 4, j = r & 15;
        float wv = W2g[E][j * 16 + k];
        float hi = trhi(wv), lo = wv - hi;
        char* bz = sm + SM_ZB + E * 1536;
        *(__nv_bfloat16*)(bz + k * 48 + j * 2)       = __float2bfloat16(hi);
        *(__nv_bfloat16*)(bz + 768 + k * 48 + j * 2) = __float2bfloat16(lo);
    }
    // BAB cols: [a0-7 | b0-7 | a8-15 | b8-15], stride 80
    for (int idx = t; idx < 1024; idx += 128) {
        int E = idx >> 9, r = idx & 511, k = r >> 5, cc = r & 31;
        int j = (cc & 7) + 8 * (cc >> 4);
        int v = (cc >> 3) & 1;
        float wv = W2g[E][j * 16 + k] * W1g[E][2 * k + v];
        float hi = trhi(wv), lo = wv - hi;
        char* bb = sm + SM_ABB + E * 2560;
        *(__nv_bfloat16*)(bb + k * 80 + cc * 2)        = __float2bfloat16(hi);
        *(__nv_bfloat16*)(bb + 1280 + k * 80 + cc * 2) = __float2bfloat16(lo);
    }
    // B3: 48 rows x 8 cols (16B/row)
    for (int idx = t; idx < 768; idx += 128) {
        int E = idx / 384, r = idx % 384, k = r >> 3, cc = r & 7;
        int chunk = k >> 4, j = k & 15;
        float w30 = W3g[E][j], w31 = W3g[E][16 + j];
        float v = 0.f;
        if (chunk == 0) v = (cc == 0) ? w30 : (cc == 1) ? w31 : 0.f;
        else if (chunk == 1) v = (cc == 2) ? w30 : (cc == 4) ? w31 : 0.f;
        else v = (cc == 3) ? w30 : (cc == 5) ? w31 : 0.f;
        float hi = trhi(v), lo = v - hi;
        char* b3 = sm + SM_B3 + E * 1536;
        *(__nv_bfloat16*)(b3 + k * 16 + cc * 2)       = __float2bfloat16(hi);
        *(__nv_bfloat16*)(b3 + 768 + k * 16 + cc * 2) = __float2bfloat16(lo);
    }
    {
        const float* B2g[2] = {eb2, db2};
        const float* B3g[2] = {eb3, db3};
        float* ewf = (float*)(sm + SM_EWF);
        if (t < 32) {
            int E = t >> 4, j = t & 15;
            ewf[E * 18 + j] = B2g[E][j];
            if (j < 2) ewf[E * 18 + 16 + j] = B3g[E][j];
        }
    }
    __syncthreads();

    const int l = t & 31, w = t >> 5;
    PC c;
    c.l = l; c.m = l & 3; c.g = l >> 2;
    c.own = 8 * c.m + c.g;
    const int ti = l >> 3, ri = l & 7;
    char* stgW = sm + SM_STG + w * 32 * STG_STRIDE;
    c.rowPtr = stgW + c.own * STG_STRIDE;
    c.aBase  = s2u(stgW) + (8 * (ti & 1) + ri) * STG_STRIDE + (ti >> 1) * 16;
    c.zBase  = s2u(sm + SM_ZB)  + (8 * (ti & 1) + ri) * 48 + (ti >> 1) * 16;
    c.abBase = s2u(sm + SM_ABB) + (8 * (ti & 1) + ri) * 80 + (ti >> 1) * 16;
    c.b3Base  = s2u(sm + SM_B3) + l * 16;              // rows 0-31 (x4)
    c.b3Base2 = s2u(sm + SM_B3) + (32 + (l & 15)) * 16; // rows 32-47 (x2)
    c.smp = sm;

    const size_t Ns = (size_t)N;
#pragma unroll
    for (int tile = 0; tile < 2; ++tile) {
        const int tb = blockIdx.x * 256 + w * 64 + tile * 32;
        const int nown = tb + c.own;
        float2 qv = make_float2(0.f, 0.f);
        if (nown < N) qv = reinterpret_cast<const float2*>(q)[nown];

        float th0 = 0.f, th1 = 0.f, dum0, dum1;
        phase(c, 0, true,  qv.x, qv.y, tb, N, out, th0, th1);
        phase(c, 1, false, th0, th1, tb, N, out, dum0, dum1);

        if (nown < N) {
            float q0 = qv.x, q1 = qv.y;
            float r2  = fmaf(q0, q0, q1 * q1);
            float inv = __fdividef(1.0f, r2);
            float isr = rsqrtf(r2 + 1e-8f);
            reinterpret_cast<float4*>(out + 12 * Ns)[nown] =
                make_float4(-q1 * inv, q0 * inv, q0 * isr, q1 * isr);
        }
    }
}

__global__ void prep_kernel(
    const float* __restrict__ ew1, const float* __restrict__ eb1,
    const float* __restrict__ dw1, const float* __restrict__ db1)
{
    const int t = threadIdx.x;
    const float* W1[2] = {ew1, dw1};
    const float* B1[2] = {eb1, db1};
    if (t < 32) {
        int E = t >> 4, i = t & 15;
        g_scr[E * 48 + 2 * i]     = W1[E][2 * i];
        g_scr[E * 48 + 2 * i + 1] = W1[E][2 * i + 1];
        g_scr[E * 48 + 32 + i]    = B1[E][i];
    }
}

extern "C" void kernel_launch(void* const* d_in, const int* in_sizes, int n_in,
                              void* d_out, int out_size) {
    prep_kernel<<<1, 32>>>((const float*)d_in[1], (const float*)d_in[2],
                           (const float*)d_in[7], (const float*)d_in[8]);
    void* cw = nullptr; void* sc = nullptr;
    cudaGetSymbolAddress(&cw, CWf);
    cudaGetSymbolAddress(&sc, g_scr);
    cudaMemcpyAsync(cw, sc, 96 * sizeof(float), cudaMemcpyDeviceToDevice, 0);

    const int N = in_sizes[0] / 2;
    const int blocks = (N + 255) / 256;
    ae_mma_kernel<<<blocks, 128>>>(
        (const float*)d_in[0],
        (const float*)d_in[1], (const float*)d_in[2],
        (const float*)d_in[3], (const float*)d_in[4],
        (const float*)d_in[5], (const float*)d_in[6],
        (const float*)d_in[7], (const float*)d_in[8],
        (const float*)d_in[9], (const float*)d_in[10],
        (const float*)d_in[11], (const float*)d_in[12],
        (float*)d_out, N);
}

// round 14
// speedup vs baseline: 1.2220x; 1.2220x over previous
#include <cuda_runtime.h>

// Fused autoencoder forward + Jacobians (R5 structure + LDCU.128 weight loads).
// 1 sample/thread; scalar value chain + f32x2-packed tangent pair (ta,tb).
// Weights in __constant__, packed so each inner fetch is one 128-bit LDCU:
//   w2q[j*8+p] = (dup w2[j][2p], dup w2[j][2p+1])
//   w3q[j]     = (w3[0][j] dup, w3[1][j] dup)
// Outputs: theta[N,2] | J_h[N,2,2] | q_hat[N,2] | J_h_dec[N,2,2] | J_h_ana[N,2,2]

typedef unsigned long long pf;   // packed (lo,hi) f32 pair
union PU { pf u; float2 f; };
union QU { float4 q; struct { pf lo, hi; } p; };

__device__ __forceinline__ pf pk(float2 v)   { PU c; c.f = v; return c.u; }
__device__ __forceinline__ pf dup2(float v)  { PU c; c.f = make_float2(v, v); return c.u; }
__device__ __forceinline__ float2 up(pf u)   { PU c; c.u = u; return c.f; }
__device__ __forceinline__ pf ffma2(pf a, pf b, pf c) {
    pf d; asm("fma.rn.f32x2 %0, %1, %2, %3;" : "=l"(d) : "l"(a), "l"(b), "l"(c)); return d;
}
__device__ __forceinline__ pf fmul2(pf a, pf b) {
    pf d; asm("mul.rn.f32x2 %0, %1, %2;" : "=l"(d) : "l"(a), "l"(b)); return d;
}

struct CData {
    float4 w2q[2][128];  // [j*8+p] = (dup w2[j][2p], dup w2[j][2p+1])
    float4 w3q[2][16];   // [j] = (w30 dup, w31 dup)
    float2 w1p[2][16];   // natural (w0,w1) rows of W1
    float  b1[2][16];
    float  b2[2][16];
    float  b3[2][2];
};

__constant__ CData CW;
__device__   CData g_scratch;

// softplus h and sigmoid s (stable, 3 MUFU)
__device__ __forceinline__ void act(float z, float& h, float& s) {
    const float L2E = 1.442695041f, LN2 = 0.6931471806f;
    float t, g;
    asm("ex2.approx.ftz.f32 %0, %1;" : "=f"(t) : "f"(fabsf(z) * -L2E));
    asm("lg2.approx.ftz.f32 %0, %1;" : "=f"(g) : "f"(1.0f + t));
    h = fmaf(g, LN2, fmaxf(z, 0.0f));
    asm("ex2.approx.ftz.f32 %0, %1;" : "=f"(s) : "f"(fmaf(fminf(z, 0.0f), L2E, -g)));
}

// MLP 2->16->16->2 softplus. Forward values scalar; Jacobian rows packed:
// rj0=(J00,J01), rj1=(J10,J11).  E=0 encoder, E=1 decoder.
template<int E>
__device__ __forceinline__ void mlp_jac(
    float x0, float x1,
    float& y0, float& y1, pf& rj0, pf& rj1)
{
    float h[16];
    pf tab[16];
#pragma unroll
    for (int i = 0; i < 16; ++i) {
        float2 w = CW.w1p[E][i];
        float z = fmaf(w.x, x0, fmaf(w.y, x1, CW.b1[E][i]));
        float hh, s;
        act(z, hh, s);
        h[i]   = hh;
        tab[i] = fmul2(dup2(s), pk(w));   // (ta,tb) = s*(w0,w1)
    }

    float acc0 = CW.b3[E][0], acc1 = CW.b3[E][1];
    pf j0 = 0, j1 = 0;                    // (J00,J01), (J10,J11)
#pragma unroll
    for (int j = 0; j < 16; ++j) {
        float z = CW.b2[E][j];
        pf ab = 0;
#pragma unroll
        for (int p = 0; p < 8; ++p) {
            QU w; w.q = CW.w2q[E][8 * j + p];   // one LDCU.128
            z  = fmaf(w.q.x, h[2 * p],     z);
            ab = ffma2(w.p.lo, tab[2 * p],     ab);
            z  = fmaf(w.q.z, h[2 * p + 1], z);
            ab = ffma2(w.p.hi, tab[2 * p + 1], ab);
        }
        float hh, s;
        act(z, hh, s);
        pf sab = fmul2(dup2(s), ab);          // (s*a, s*b)
        QU w3; w3.q = CW.w3q[E][j];            // one LDCU.128
        acc0 = fmaf(w3.q.x, hh, acc0);
        acc1 = fmaf(w3.q.z, hh, acc1);
        j0 = ffma2(w3.p.lo, sab, j0);
        j1 = ffma2(w3.p.hi, sab, j1);
    }
    y0 = acc0; y1 = acc1; rj0 = j0; rj1 = j1;
}

__global__ void __launch_bounds__(256) prep_kernel(
    const float* __restrict__ ew1, const float* __restrict__ eb1,
    const float* __restrict__ ew2, const float* __restrict__ eb2,
    const float* __restrict__ ew3, const float* __restrict__ eb3,
    const float* __restrict__ dw1, const float* __restrict__ db1,
    const float* __restrict__ dw2, const float* __restrict__ db2,
    const float* __restrict__ dw3, const float* __restrict__ db3)
{
    const int t = threadIdx.x;
    const float* W1[2] = {ew1, dw1};
    const float* B1[2] = {eb1, db1};
    const float* W2[2] = {ew2, dw2};
    const float* B2[2] = {eb2, db2};
    const float* W3[2] = {ew3, dw3};
    const float* B3[2] = {eb3, db3};

#pragma unroll
    for (int E = 0; E < 2; ++E) {
        if (t < 128) {
            int j = t >> 3, p = t & 7;
            float wa = W2[E][j * 16 + 2 * p];
            float wb = W2[E][j * 16 + 2 * p + 1];
            g_scratch.w2q[E][t] = make_float4(wa, wa, wb, wb);
        }
        if (t < 16) {
            float w30 = W3[E][t], w31 = W3[E][16 + t];
            g_scratch.w3q[E][t] = make_float4(w30, w30, w31, w31);
            g_scratch.w1p[E][t] = make_float2(W1[E][2 * t], W1[E][2 * t + 1]);
            g_scratch.b1[E][t] = B1[E][t];
            g_scratch.b2[E][t] = B2[E][t];
        }
        if (t < 2) g_scratch.b3[E][t] = B3[E][t];
    }
}

__global__ void __launch_bounds__(256) ae_kernel(
    const float* __restrict__ q, float* __restrict__ out, int N)
{
    const int n = blockIdx.x * 256 + threadIdx.x;
    if (n >= N) return;

    const float2 qv = reinterpret_cast<const float2*>(q)[n];
    const float q0 = qv.x, q1 = qv.y;

    // analytic jacobian
    const float r2  = fmaf(q0, q0, q1 * q1);
    const float inv = __fdividef(1.0f, r2);
    const float isr = rsqrtf(r2 + 1e-8f);
    const float ja00 = -q1 * inv;
    const float ja01 =  q0 * inv;
    const float ja10 =  q0 * isr;
    const float ja11 =  q1 * isr;

    float th0, th1, qh0, qh1;
    pf jh0, jh1, jd0, jd1;
    mlp_jac<0>(q0, q1, th0, th1, jh0, jh1);
    mlp_jac<1>(th0, th1, qh0, qh1, jd0, jd1);

    const size_t Ns = (size_t)N;
    float2* o_theta = reinterpret_cast<float2*>(out);
    pf*     o_jh    = reinterpret_cast<pf*>(out + 2 * Ns);
    float2* o_qhat  = reinterpret_cast<float2*>(out + 6 * Ns);
    pf*     o_jd    = reinterpret_cast<pf*>(out + 8 * Ns);
    float4* o_ja    = reinterpret_cast<float4*>(out + 12 * Ns);

    o_theta[n]      = make_float2(th0, th1);
    o_jh[2 * n]     = jh0;               // (J00,J01)
    o_jh[2 * n + 1] = jh1;               // (J10,J11)
    o_qhat[n]       = make_float2(qh0, qh1);
    o_jd[2 * n]     = jd0;
    o_jd[2 * n + 1] = jd1;
    o_ja[n]         = make_float4(ja00, ja01, ja10, ja11);
}

extern "C" void kernel_launch(void* const* d_in, const int* in_sizes, int n_in,
                              void* d_out, int out_size) {
    const float* q = (const float*)d_in[0];

    prep_kernel<<<1, 256>>>(
        (const float*)d_in[1], (const float*)d_in[2],
        (const float*)d_in[3], (const float*)d_in[4],
        (const float*)d_in[5], (const float*)d_in[6],
        (const float*)d_in[7], (const float*)d_in[8],
        (const float*)d_in[9], (const float*)d_in[10],
        (const float*)d_in[11], (const float*)d_in[12]);

    void* cw_addr = nullptr;
    void* sc_addr = nullptr;
    cudaGetSymbolAddress(&cw_addr, CW);
    cudaGetSymbolAddress(&sc_addr, g_scratch);
    cudaMemcpyAsync(cw_addr, sc_addr, sizeof(CData),
                    cudaMemcpyDeviceToDevice, 0);

    const int N = in_sizes[0] / 2;
    const int blocks = (N + 255) / 256;
    ae_kernel<<<blocks, 256>>>(q, (float*)d_out, N);
}